// round 5
// baseline (speedup 1.0000x reference)
#include <cuda_runtime.h>
#include <math.h>

// Problem constants (match reference)
#define NXc 201
#define NYc 121
#define NZc 80
#define VPB (NXc * NYc * NZc)      // 1,945,680
#define BATCH 4
#define NVOX (VPB * BATCH)         // 7,782,720
#define HH 512
#define WW 1024
#define NPTS (HH * WW)             // 524,288 per batch
#define TOT (BATCH * NPTS)         // 2,097,152
#define LOG32F 3.4657359027997265f

// Scratch: packed accumulators (count, z_sum, rel_sum, geom_sum) per voxel
__device__ float4 g_acc[NVOX];
__device__ int    g_seg[TOT];
__device__ unsigned int g_min[BATCH];
__device__ unsigned int g_max[BATCH];

// ---------------- K1: zero accumulators + init min/max ----------------
__global__ void k_zero() {
    int idx = blockIdx.x * blockDim.x + threadIdx.x;
    if (idx < NVOX) {
        g_acc[idx] = make_float4(0.f, 0.f, 0.f, 0.f);
    }
    if (idx < BATCH) {
        g_min[idx] = 0x7F800000u;  // +inf
        g_max[idx] = 0u;           // 0.0f (scores are >= 0)
    }
}

// ---------------- K2: scatter points into voxel grid ----------------
__global__ void k_scatter(const float* __restrict__ xyz,
                          const float* __restrict__ rel,
                          const float* __restrict__ geom) {
    int i = blockIdx.x * blockDim.x + threadIdx.x;
    if (i >= TOT) return;
    int b = i / NPTS;
    int p = i - b * NPTS;
    const float* base = xyz + (long long)b * 3 * NPTS;
    float x = base[p];
    float y = base[p + NPTS];
    float z = base[p + 2 * NPTS];
    float r = rel[i];
    float g = geom[i];

    bool keep = (x >= -10.0f) & (x <= 10.0f) &
                (y >= -6.0f)  & (y <= 6.0f)  &
                (z >= 0.3f)   & (z <= 20.0f) &
                (r > 0.0f);

    int seg = -1;
    if (keep) {
        // XLA canonicalizes (v - lo) / c into (v - lo) * round_f32(1/c).
        // round_f32(1/0.1f)  = 10.0 exactly (9.99999985 rounds UP to 10.0)
        // round_f32(1/0.25f) = 4.0  exactly
        float fx = floorf(__fmul_rn(__fadd_rn(x, 10.0f), 10.0f));
        float fy = floorf(__fmul_rn(__fadd_rn(y, 6.0f),  10.0f));
        float fz = floorf(__fmul_rn(__fsub_rn(z, 0.3f),  4.0f));
        int ix = min(max((int)fx, 0), NXc - 1);
        int iy = min(max((int)fy, 0), NYc - 1);
        int iz = min(max((int)fz, 0), NZc - 1);
        seg = (ix * NYc + iy) * NZc + iz + b * VPB;
        float* a = (float*)&g_acc[seg];
        atomicAdd(a + 0, 1.0f);
        atomicAdd(a + 1, z);
        atomicAdd(a + 2, r);
        atomicAdd(a + 3, g);
    }
    g_seg[i] = seg;
}

// ---------------- K3: gather + score + per-batch min/max ----------------
__global__ void k_score(float* __restrict__ out) {
    int i = blockIdx.x * blockDim.x + threadIdx.x;
    // NPTS % blockDim == 0, so every block lies within a single batch item
    float s = 0.0f;
    if (i < TOT) {
        int seg = g_seg[i];
        if (seg >= 0) {
            float4 a = g_acc[seg];
            float cc  = fmaxf(a.x, 1.0f);
            // Non-constant divisors: IEEE divide
            float z_mean    = __fdiv_rn(a.y, cc);
            float rel_mean  = __fdiv_rn(a.z, cc);
            float geom_mean = __fdiv_rn(a.w, cc);
            float density   = __fmul_rn(log1pf(a.x), (1.0f / LOG32F));
            float range_sc  = expf(__fmul_rn(-0.08f, z_mean));
            float t = __fadd_rn(__fadd_rn(__fmul_rn(0.55f, geom_mean),
                                          __fmul_rn(0.25f, density)),
                                __fmul_rn(0.2f, range_sc));
            s = fmaxf(__fmul_rn(t, rel_mean), 0.0f);
        }
        out[i] = s;
    }

    // block min/max reduce (values are nonneg floats -> uint ordering works)
    float vmin = (i < TOT) ? s : __int_as_float(0x7F800000);
    float vmax = (i < TOT) ? s : 0.0f;
    #pragma unroll
    for (int off = 16; off > 0; off >>= 1) {
        vmin = fminf(vmin, __shfl_xor_sync(0xFFFFFFFFu, vmin, off));
        vmax = fmaxf(vmax, __shfl_xor_sync(0xFFFFFFFFu, vmax, off));
    }
    __shared__ float smin[8], smax[8];
    int warp = threadIdx.x >> 5;
    int lane = threadIdx.x & 31;
    if (lane == 0) { smin[warp] = vmin; smax[warp] = vmax; }
    __syncthreads();
    if (threadIdx.x == 0) {
        float bmin = smin[0], bmax = smax[0];
        int nwarp = blockDim.x >> 5;
        for (int w = 1; w < nwarp; w++) {
            bmin = fminf(bmin, smin[w]);
            bmax = fmaxf(bmax, smax[w]);
        }
        int b = (blockIdx.x * blockDim.x) / NPTS;
        atomicMin(&g_min[b], __float_as_uint(bmin));
        atomicMax(&g_max[b], __float_as_uint(bmax));
    }
}

// ---------------- K4: normalize in place ----------------
__global__ void k_norm(float* __restrict__ out) {
    int i = blockIdx.x * blockDim.x + threadIdx.x;
    if (i >= TOT) return;
    int b = i / NPTS;
    float mn = __uint_as_float(g_min[b]);
    float mx = __uint_as_float(g_max[b]);
    float denom = __fadd_rn(__fsub_rn(mx, mn), 1e-6f);
    out[i] = __fdiv_rn(__fsub_rn(out[i], mn), denom);
}

extern "C" void kernel_launch(void* const* d_in, const int* in_sizes, int n_in,
                              void* d_out, int out_size) {
    const float* xyz  = (const float*)d_in[0];
    const float* rel  = (const float*)d_in[1];
    const float* geom = (const float*)d_in[2];
    float* out = (float*)d_out;

    const int T = 256;
    k_zero<<<(NVOX + T - 1) / T, T>>>();
    k_scatter<<<(TOT + T - 1) / T, T>>>(xyz, rel, geom);
    k_score<<<(TOT + T - 1) / T, T>>>(out);
    k_norm<<<(TOT + T - 1) / T, T>>>(out);
}

// round 6
// speedup vs baseline: 1.2724x; 1.2724x over previous
#include <cuda_runtime.h>
#include <math.h>

// Problem constants (match reference)
#define NXc 201
#define NYc 121
#define NZc 80
#define VPB (NXc * NYc * NZc)      // 1,945,680
#define BATCH 4
#define NVOX (VPB * BATCH)         // 7,782,720
#define HH 512
#define WW 1024
#define NPTS (HH * WW)             // 524,288 per batch (2^19)
#define TOT (BATCH * NPTS)         // 2,097,152
#define LOG32F 3.4657359027997265f

// Scratch: packed accumulators (count, z_sum, rel_sum, geom_sum) per voxel.
// INVARIANT: g_acc is all-zero and g_min/g_max are at sentinel values on entry
// to kernel_launch. Established by static zero-init / initializers at module
// load; re-established by k_clear at the end of every launch (graph-replay safe).
__device__ float4 g_acc[NVOX];                 // zero-initialized at load
__device__ int    g_seg[TOT];
__device__ unsigned int g_min[BATCH] = {0x7F800000u, 0x7F800000u, 0x7F800000u, 0x7F800000u};
__device__ unsigned int g_max[BATCH] = {0u, 0u, 0u, 0u};

// ---------------- K1: scatter points into voxel grid ----------------
__global__ void k_scatter(const float* __restrict__ xyz,
                          const float* __restrict__ rel,
                          const float* __restrict__ geom) {
    int i = blockIdx.x * blockDim.x + threadIdx.x;
    if (i >= TOT) return;
    int b = i >> 19;           // i / NPTS
    int p = i & (NPTS - 1);
    const float* base = xyz + (long long)b * 3 * NPTS;
    float x = base[p];
    float y = base[p + NPTS];
    float z = base[p + 2 * NPTS];
    float r = rel[i];
    float g = geom[i];

    bool keep = (x >= -10.0f) & (x <= 10.0f) &
                (y >= -6.0f)  & (y <= 6.0f)  &
                (z >= 0.3f)   & (z <= 20.0f) &
                (r > 0.0f);

    int seg = -1;
    if (keep) {
        // XLA canonicalizes (v - lo) / c into (v - lo) * round_f32(1/c).
        // round_f32(1/0.1f) = 10.0 exactly; round_f32(1/0.25f) = 4.0 exactly.
        // This MUST stay bit-exact (voxel boundary flips dominate rel_err).
        float fx = floorf(__fmul_rn(__fadd_rn(x, 10.0f), 10.0f));
        float fy = floorf(__fmul_rn(__fadd_rn(y, 6.0f),  10.0f));
        float fz = floorf(__fmul_rn(__fsub_rn(z, 0.3f),  4.0f));
        int ix = min(max((int)fx, 0), NXc - 1);
        int iy = min(max((int)fy, 0), NYc - 1);
        int iz = min(max((int)fz, 0), NZc - 1);
        seg = (ix * NYc + iy) * NZc + iz + b * VPB;
        float* a = (float*)&g_acc[seg];
        atomicAdd(a + 0, 1.0f);
        atomicAdd(a + 1, z);
        atomicAdd(a + 2, r);
        atomicAdd(a + 3, g);
    }
    g_seg[i] = seg;
}

// ---------------- K2: gather + score + per-batch min/max ----------------
__global__ void k_score(float* __restrict__ out) {
    int i = blockIdx.x * blockDim.x + threadIdx.x;
    // NPTS % blockDim == 0, so every block lies within a single batch item
    float s = 0.0f;
    if (i < TOT) {
        int seg = g_seg[i];
        if (seg >= 0) {
            float4 a = g_acc[seg];
            float cc  = fmaxf(a.x, 1.0f);
            // Tolerance is 1e-3; only index math needs exactness. Fast paths:
            float inv = __fdividef(1.0f, cc);
            float z_mean    = a.y * inv;
            float rel_mean  = a.z * inv;
            float geom_mean = a.w * inv;
            float density   = log1pf(a.x) * (1.0f / LOG32F);
            float range_sc  = __expf(-0.08f * z_mean);
            s = (0.55f * geom_mean + 0.25f * density + 0.2f * range_sc) * rel_mean;
            s = fmaxf(s, 0.0f);
        }
        out[i] = s;
    }

    // block min/max reduce (values are nonneg floats -> uint ordering works)
    float vmin = (i < TOT) ? s : __int_as_float(0x7F800000);
    float vmax = (i < TOT) ? s : 0.0f;
    #pragma unroll
    for (int off = 16; off > 0; off >>= 1) {
        vmin = fminf(vmin, __shfl_xor_sync(0xFFFFFFFFu, vmin, off));
        vmax = fmaxf(vmax, __shfl_xor_sync(0xFFFFFFFFu, vmax, off));
    }
    __shared__ float smin[8], smax[8];
    int warp = threadIdx.x >> 5;
    int lane = threadIdx.x & 31;
    if (lane == 0) { smin[warp] = vmin; smax[warp] = vmax; }
    __syncthreads();
    if (threadIdx.x == 0) {
        float bmin = smin[0], bmax = smax[0];
        int nwarp = blockDim.x >> 5;
        for (int w = 1; w < nwarp; w++) {
            bmin = fminf(bmin, smin[w]);
            bmax = fmaxf(bmax, smax[w]);
        }
        int b = (blockIdx.x * blockDim.x) >> 19;
        atomicMin(&g_min[b], __float_as_uint(bmin));
        atomicMax(&g_max[b], __float_as_uint(bmax));
    }
}

// ---------------- K3: normalize in place (float4, rcp-multiply) ----------------
__global__ void k_norm(float4* __restrict__ out) {
    int i = blockIdx.x * blockDim.x + threadIdx.x;       // float4 index
    if (i >= TOT / 4) return;
    int b = i >> 17;                                     // (i*4) / NPTS
    float mn = __uint_as_float(g_min[b]);
    float mx = __uint_as_float(g_max[b]);
    float inv = __fdividef(1.0f, (mx - mn) + 1e-6f);
    float4 v = out[i];
    v.x = (v.x - mn) * inv;
    v.y = (v.y - mn) * inv;
    v.z = (v.z - mn) * inv;
    v.w = (v.w - mn) * inv;
    out[i] = v;
}

// ---------------- K4: restore invariant (zero touched voxels, reset min/max) ----
__global__ void k_clear() {
    int i = blockIdx.x * blockDim.x + threadIdx.x;
    if (i < TOT) {
        int seg = g_seg[i];
        if (seg >= 0) {
            g_acc[seg] = make_float4(0.f, 0.f, 0.f, 0.f);  // races write same value
        }
    }
    if (i < BATCH) {
        g_min[i] = 0x7F800000u;
        g_max[i] = 0u;
    }
}

extern "C" void kernel_launch(void* const* d_in, const int* in_sizes, int n_in,
                              void* d_out, int out_size) {
    const float* xyz  = (const float*)d_in[0];
    const float* rel  = (const float*)d_in[1];
    const float* geom = (const float*)d_in[2];
    float* out = (float*)d_out;

    const int T = 256;
    k_scatter<<<(TOT + T - 1) / T, T>>>(xyz, rel, geom);
    k_score<<<(TOT + T - 1) / T, T>>>(out);
    k_norm<<<(TOT / 4 + T - 1) / T, T>>>((float4*)out);
    k_clear<<<(TOT + T - 1) / T, T>>>();
}

// round 8
// speedup vs baseline: 1.6044x; 1.2609x over previous
#include <cuda_runtime.h>
#include <math.h>

// Problem constants (match reference)
#define NXc 201
#define NYc 121
#define NZc 80
#define VPB (NXc * NYc * NZc)      // 1,945,680
#define BATCH 4
#define HH 512
#define WW 1024
#define NPTS (HH * WW)             // 524,288 per batch (2^19)
#define TOT (BATCH * NPTS)         // 2,097,152
#define NVOX (VPB * BATCH)         // 7,782,720
#define LOG32F 3.4657359027997265f

// Scratch. INVARIANT: g_acc all-zero on entry to kernel_launch (zero-init at
// load; re-established by k_norm_clear each launch). g_min/g_max are re-armed
// at the start of each launch by k_scatter, BEFORE k_score uses them.
__device__ float4 g_acc[NVOX];
__device__ int    g_seg[TOT];
__device__ unsigned int g_min[BATCH];
__device__ unsigned int g_max[BATCH];

// sm_90+ vector reduction: one instruction updates all 4 accumulators
__device__ __forceinline__ void red_add_v4(float4* addr, float c, float z, float r, float g) {
    asm volatile("red.global.add.v4.f32 [%0], {%1, %2, %3, %4};"
                 :: "l"(addr), "f"(c), "f"(z), "f"(r), "f"(g) : "memory");
}

// ---------------- K1: scatter (4 points/thread, vector atomics) ----------------
__global__ void k_scatter(const float* __restrict__ xyz,
                          const float4* __restrict__ rel4,
                          const float4* __restrict__ geom4) {
    int i = blockIdx.x * blockDim.x + threadIdx.x;   // quad index

    // Re-arm per-batch min/max sentinels for this launch. Safe: nothing in
    // this kernel reads them; k_score (the consumer) runs after we finish.
    if (i < BATCH) {
        g_min[i] = 0x7F800000u;   // +inf
        g_max[i] = 0u;            // 0.0f (scores are >= 0)
    }

    if (i >= TOT / 4) return;
    int p4 = (i << 2) & (NPTS - 1);                  // point offset within batch
    int b  = i >> 17;                                // (i*4) / NPTS
    const float* base = xyz + (long long)b * 3 * NPTS;
    float4 x = *(const float4*)(base + p4);
    float4 y = *(const float4*)(base + p4 + NPTS);
    float4 z = *(const float4*)(base + p4 + 2 * NPTS);
    float4 r = rel4[i];
    float4 g = geom4[i];

    int seg[4];
    float xs[4] = {x.x, x.y, x.z, x.w};
    float ys[4] = {y.x, y.y, y.z, y.w};
    float zs[4] = {z.x, z.y, z.z, z.w};
    float rs[4] = {r.x, r.y, r.z, r.w};
    float gs[4] = {g.x, g.y, g.z, g.w};

    #pragma unroll
    for (int k = 0; k < 4; k++) {
        bool keep = (xs[k] >= -10.0f) & (xs[k] <= 10.0f) &
                    (ys[k] >= -6.0f)  & (ys[k] <= 6.0f)  &
                    (zs[k] >= 0.3f)   & (zs[k] <= 20.0f) &
                    (rs[k] > 0.0f);
        seg[k] = -1;
        if (keep) {
            // Bit-exact vs XLA: (v - lo) * round_f32(1/c); 1/0.1f -> 10.0,
            // 1/0.25f -> 4.0, both exact in f32.
            float fx = floorf(__fmul_rn(__fadd_rn(xs[k], 10.0f), 10.0f));
            float fy = floorf(__fmul_rn(__fadd_rn(ys[k], 6.0f),  10.0f));
            float fz = floorf(__fmul_rn(__fsub_rn(zs[k], 0.3f),  4.0f));
            int ix = min(max((int)fx, 0), NXc - 1);
            int iy = min(max((int)fy, 0), NYc - 1);
            int iz = min(max((int)fz, 0), NZc - 1);
            seg[k] = (ix * NYc + iy) * NZc + iz + b * VPB;
        }
    }
    // issue all atomics back-to-back for MLP
    #pragma unroll
    for (int k = 0; k < 4; k++)
        if (seg[k] >= 0)
            red_add_v4(&g_acc[seg[k]], 1.0f, zs[k], rs[k], gs[k]);

    ((int4*)g_seg)[i] = make_int4(seg[0], seg[1], seg[2], seg[3]);
}

// ---------------- K2: gather + score + per-batch min/max (4 pts/thread) --------
__global__ void k_score(float4* __restrict__ out4) {
    int i = blockIdx.x * blockDim.x + threadIdx.x;   // quad index
    float s[4] = {0.f, 0.f, 0.f, 0.f};
    if (i < TOT / 4) {
        int4 sg = ((const int4*)g_seg)[i];
        int seg[4] = {sg.x, sg.y, sg.z, sg.w};
        float4 a[4];
        #pragma unroll
        for (int k = 0; k < 4; k++)
            a[k] = (seg[k] >= 0) ? g_acc[seg[k]] : make_float4(0.f, 0.f, 0.f, 0.f);
        #pragma unroll
        for (int k = 0; k < 4; k++) {
            if (seg[k] >= 0) {
                float cc  = fmaxf(a[k].x, 1.0f);
                float inv = __fdividef(1.0f, cc);
                float z_mean    = a[k].y * inv;
                float rel_mean  = a[k].z * inv;
                float geom_mean = a[k].w * inv;
                float density   = log1pf(a[k].x) * (1.0f / LOG32F);
                float range_sc  = __expf(-0.08f * z_mean);
                float t = 0.55f * geom_mean + 0.25f * density + 0.2f * range_sc;
                s[k] = fmaxf(t * rel_mean, 0.0f);
            }
        }
        out4[i] = make_float4(s[0], s[1], s[2], s[3]);
    }

    // block min/max reduce (nonneg floats -> uint ordering works)
    float vmin = __int_as_float(0x7F800000), vmax = 0.0f;
    if (i < TOT / 4) {
        vmin = fminf(fminf(s[0], s[1]), fminf(s[2], s[3]));
        vmax = fmaxf(fmaxf(s[0], s[1]), fmaxf(s[2], s[3]));
    }
    #pragma unroll
    for (int off = 16; off > 0; off >>= 1) {
        vmin = fminf(vmin, __shfl_xor_sync(0xFFFFFFFFu, vmin, off));
        vmax = fmaxf(vmax, __shfl_xor_sync(0xFFFFFFFFu, vmax, off));
    }
    __shared__ float smin[8], smax[8];
    int warp = threadIdx.x >> 5;
    int lane = threadIdx.x & 31;
    if (lane == 0) { smin[warp] = vmin; smax[warp] = vmax; }
    __syncthreads();
    if (threadIdx.x == 0) {
        float bmin = smin[0], bmax = smax[0];
        int nwarp = blockDim.x >> 5;
        for (int w = 1; w < nwarp; w++) {
            bmin = fminf(bmin, smin[w]);
            bmax = fmaxf(bmax, smax[w]);
        }
        int b = (blockIdx.x * blockDim.x) >> 17;   // quad index -> batch
        atomicMin(&g_min[b], __float_as_uint(bmin));
        atomicMax(&g_max[b], __float_as_uint(bmax));
    }
}

// ---------------- K3: fused normalize + g_acc invariant restore ----------------
__global__ void k_norm_clear(float4* __restrict__ out4) {
    int i = blockIdx.x * blockDim.x + threadIdx.x;   // quad index
    if (i >= TOT / 4) return;

    // clear touched voxels (latency-bound scattered stores, 4 in flight)
    int4 sg = ((const int4*)g_seg)[i];
    float4 zero = make_float4(0.f, 0.f, 0.f, 0.f);
    if (sg.x >= 0) g_acc[sg.x] = zero;
    if (sg.y >= 0) g_acc[sg.y] = zero;
    if (sg.z >= 0) g_acc[sg.z] = zero;
    if (sg.w >= 0) g_acc[sg.w] = zero;

    // normalize (streaming). g_min/g_max are stable here; they are only
    // re-armed by the NEXT launch's k_scatter.
    int b = i >> 17;
    float mn = __uint_as_float(g_min[b]);
    float mx = __uint_as_float(g_max[b]);
    float inv = __fdividef(1.0f, (mx - mn) + 1e-6f);
    float4 v = out4[i];
    v.x = (v.x - mn) * inv;
    v.y = (v.y - mn) * inv;
    v.z = (v.z - mn) * inv;
    v.w = (v.w - mn) * inv;
    out4[i] = v;
}

extern "C" void kernel_launch(void* const* d_in, const int* in_sizes, int n_in,
                              void* d_out, int out_size) {
    const float* xyz  = (const float*)d_in[0];
    const float* rel  = (const float*)d_in[1];
    const float* geom = (const float*)d_in[2];
    float* out = (float*)d_out;

    const int T = 256;
    const int Q = TOT / 4;
    k_scatter<<<(Q + T - 1) / T, T>>>(xyz, (const float4*)rel, (const float4*)geom);
    k_score<<<(Q + T - 1) / T, T>>>((float4*)out);
    k_norm_clear<<<(Q + T - 1) / T, T>>>((float4*)out);
}

// round 9
// speedup vs baseline: 1.8087x; 1.1273x over previous
#include <cuda_runtime.h>
#include <math.h>

// Problem constants (match reference)
#define NXc 201
#define NYc 121
#define NZc 80
#define VPB (NXc * NYc * NZc)      // 1,945,680
#define BATCH 4
#define HH 512
#define WW 1024
#define NPTS (HH * WW)             // 524,288 per batch (2^19)
#define TOT (BATCH * NPTS)         // 2,097,152
#define NVOX (VPB * BATCH)         // 7,782,720
#define LOG32F 3.4657359027997265f

// Scratch. INVARIANT: g_acc all-zero on entry to kernel_launch (zero-init at
// load; re-established by k_norm_clear each launch). g_min/g_max are re-armed
// at the start of each launch by k_scatter, BEFORE k_score uses them.
__device__ float4 g_acc[NVOX];
__device__ int    g_seg[TOT];
__device__ unsigned int g_min[BATCH];
__device__ unsigned int g_max[BATCH];

// L2 evict_last policy: keep g_acc lines resident across kernels & replays
__device__ __forceinline__ unsigned long long plc_last() {
    unsigned long long p;
    asm("createpolicy.fractional.L2::evict_last.b64 %0, 1.0;" : "=l"(p));
    return p;
}

// Vector reduction with L2 retain hint
__device__ __forceinline__ void red_add_v4(float4* addr, float c, float z, float r, float g,
                                           unsigned long long pol) {
    asm volatile("red.global.add.L2::cache_hint.v4.f32 [%0], {%1, %2, %3, %4}, %5;"
                 :: "l"(addr), "f"(c), "f"(z), "f"(r), "f"(g), "l"(pol) : "memory");
}

// Gather with L2 retain hint
__device__ __forceinline__ float4 ld_acc(const float4* addr, unsigned long long pol) {
    float4 v;
    asm("ld.global.nc.L2::cache_hint.v4.f32 {%0, %1, %2, %3}, [%4], %5;"
        : "=f"(v.x), "=f"(v.y), "=f"(v.z), "=f"(v.w) : "l"(addr), "l"(pol));
    return v;
}

// Clear store with L2 retain hint (lines stay hot for next replay's scatter)
__device__ __forceinline__ void st_acc_zero(float4* addr, unsigned long long pol) {
    asm volatile("st.global.L2::cache_hint.v4.f32 [%0], {%1, %1, %1, %1}, %2;"
                 :: "l"(addr), "f"(0.0f), "l"(pol) : "memory");
}

// ---------------- K1: scatter (4 points/thread, vector atomics) ----------------
__global__ void k_scatter(const float* __restrict__ xyz,
                          const float4* __restrict__ rel4,
                          const float4* __restrict__ geom4) {
    int i = blockIdx.x * blockDim.x + threadIdx.x;   // quad index

    // Re-arm per-batch min/max sentinels for this launch (consumer k_score
    // runs strictly after this kernel).
    if (i < BATCH) {
        g_min[i] = 0x7F800000u;   // +inf
        g_max[i] = 0u;            // 0.0f (scores are >= 0)
    }

    if (i >= TOT / 4) return;
    unsigned long long pol = plc_last();
    int p4 = (i << 2) & (NPTS - 1);                  // point offset within batch
    int b  = i >> 17;                                // (i*4) / NPTS
    const float* base = xyz + (long long)b * 3 * NPTS;
    float4 x = __ldcs((const float4*)(base + p4));
    float4 y = __ldcs((const float4*)(base + p4 + NPTS));
    float4 z = __ldcs((const float4*)(base + p4 + 2 * NPTS));
    float4 r = __ldcs(rel4 + i);
    float4 g = __ldcs(geom4 + i);

    int seg[4];
    float xs[4] = {x.x, x.y, x.z, x.w};
    float ys[4] = {y.x, y.y, y.z, y.w};
    float zs[4] = {z.x, z.y, z.z, z.w};
    float rs[4] = {r.x, r.y, r.z, r.w};

    #pragma unroll
    for (int k = 0; k < 4; k++) {
        bool keep = (xs[k] >= -10.0f) & (xs[k] <= 10.0f) &
                    (ys[k] >= -6.0f)  & (ys[k] <= 6.0f)  &
                    (zs[k] >= 0.3f)   & (zs[k] <= 20.0f) &
                    (rs[k] > 0.0f);
        seg[k] = -1;
        if (keep) {
            // Bit-exact vs XLA: (v - lo) * round_f32(1/c); 1/0.1f -> 10.0,
            // 1/0.25f -> 4.0, both exact in f32.
            float fx = floorf(__fmul_rn(__fadd_rn(xs[k], 10.0f), 10.0f));
            float fy = floorf(__fmul_rn(__fadd_rn(ys[k], 6.0f),  10.0f));
            float fz = floorf(__fmul_rn(__fsub_rn(zs[k], 0.3f),  4.0f));
            int ix = min(max((int)fx, 0), NXc - 1);
            int iy = min(max((int)fy, 0), NYc - 1);
            int iz = min(max((int)fz, 0), NZc - 1);
            seg[k] = (ix * NYc + iy) * NZc + iz + b * VPB;
        }
    }
    float gs[4] = {g.x, g.y, g.z, g.w};
    // issue all atomics back-to-back for MLP
    #pragma unroll
    for (int k = 0; k < 4; k++)
        if (seg[k] >= 0)
            red_add_v4(&g_acc[seg[k]], 1.0f, zs[k], rs[k], gs[k], pol);

    __stcs((int4*)g_seg + i, make_int4(seg[0], seg[1], seg[2], seg[3]));
}

// ---------------- K2: gather + score + per-batch min/max (4 pts/thread) --------
__global__ void k_score(float4* __restrict__ out4) {
    int i = blockIdx.x * blockDim.x + threadIdx.x;   // quad index
    float s[4] = {0.f, 0.f, 0.f, 0.f};
    if (i < TOT / 4) {
        unsigned long long pol = plc_last();
        int4 sg = __ldcs((const int4*)g_seg + i);
        int seg[4] = {sg.x, sg.y, sg.z, sg.w};
        float4 a[4];
        #pragma unroll
        for (int k = 0; k < 4; k++)
            a[k] = (seg[k] >= 0) ? ld_acc(&g_acc[seg[k]], pol)
                                 : make_float4(0.f, 0.f, 0.f, 0.f);
        #pragma unroll
        for (int k = 0; k < 4; k++) {
            if (seg[k] >= 0) {
                float cc  = fmaxf(a[k].x, 1.0f);
                float inv = __fdividef(1.0f, cc);
                float z_mean    = a[k].y * inv;
                float rel_mean  = a[k].z * inv;
                float geom_mean = a[k].w * inv;
                float density   = log1pf(a[k].x) * (1.0f / LOG32F);
                float range_sc  = __expf(-0.08f * z_mean);
                float t = 0.55f * geom_mean + 0.25f * density + 0.2f * range_sc;
                s[k] = fmaxf(t * rel_mean, 0.0f);
            }
        }
        __stcs(out4 + i, make_float4(s[0], s[1], s[2], s[3]));
    }

    // block min/max reduce (nonneg floats -> uint ordering works)
    float vmin = __int_as_float(0x7F800000), vmax = 0.0f;
    if (i < TOT / 4) {
        vmin = fminf(fminf(s[0], s[1]), fminf(s[2], s[3]));
        vmax = fmaxf(fmaxf(s[0], s[1]), fmaxf(s[2], s[3]));
    }
    #pragma unroll
    for (int off = 16; off > 0; off >>= 1) {
        vmin = fminf(vmin, __shfl_xor_sync(0xFFFFFFFFu, vmin, off));
        vmax = fmaxf(vmax, __shfl_xor_sync(0xFFFFFFFFu, vmax, off));
    }
    __shared__ float smin[8], smax[8];
    int warp = threadIdx.x >> 5;
    int lane = threadIdx.x & 31;
    if (lane == 0) { smin[warp] = vmin; smax[warp] = vmax; }
    __syncthreads();
    if (threadIdx.x == 0) {
        float bmin = smin[0], bmax = smax[0];
        int nwarp = blockDim.x >> 5;
        for (int w = 1; w < nwarp; w++) {
            bmin = fminf(bmin, smin[w]);
            bmax = fmaxf(bmax, smax[w]);
        }
        int b = (blockIdx.x * blockDim.x) >> 17;   // quad index -> batch
        atomicMin(&g_min[b], __float_as_uint(bmin));
        atomicMax(&g_max[b], __float_as_uint(bmax));
    }
}

// ---------------- K3: fused normalize + g_acc invariant restore ----------------
__global__ void k_norm_clear(float4* __restrict__ out4) {
    int i = blockIdx.x * blockDim.x + threadIdx.x;   // quad index
    if (i >= TOT / 4) return;
    unsigned long long pol = plc_last();

    // clear touched voxels (4 scattered stores in flight; keep lines in L2 for
    // the next replay's scatter)
    int4 sg = __ldcs((const int4*)g_seg + i);
    if (sg.x >= 0) st_acc_zero(&g_acc[sg.x], pol);
    if (sg.y >= 0) st_acc_zero(&g_acc[sg.y], pol);
    if (sg.z >= 0) st_acc_zero(&g_acc[sg.z], pol);
    if (sg.w >= 0) st_acc_zero(&g_acc[sg.w], pol);

    // normalize (streaming). g_min/g_max are stable here; re-armed only by
    // the NEXT launch's k_scatter.
    int b = i >> 17;
    float mn = __uint_as_float(g_min[b]);
    float mx = __uint_as_float(g_max[b]);
    float inv = __fdividef(1.0f, (mx - mn) + 1e-6f);
    float4 v = __ldcs(out4 + i);
    v.x = (v.x - mn) * inv;
    v.y = (v.y - mn) * inv;
    v.z = (v.z - mn) * inv;
    v.w = (v.w - mn) * inv;
    __stcs(out4 + i, v);
}

extern "C" void kernel_launch(void* const* d_in, const int* in_sizes, int n_in,
                              void* d_out, int out_size) {
    const float* xyz  = (const float*)d_in[0];
    const float* rel  = (const float*)d_in[1];
    const float* geom = (const float*)d_in[2];
    float* out = (float*)d_out;

    const int T = 256;
    const int Q = TOT / 4;
    k_scatter<<<(Q + T - 1) / T, T>>>(xyz, (const float4*)rel, (const float4*)geom);
    k_score<<<(Q + T - 1) / T, T>>>((float4*)out);
    k_norm_clear<<<(Q + T - 1) / T, T>>>((float4*)out);
}